// round 10
// baseline (speedup 1.0000x reference)
#include <cuda_runtime.h>
#include <cuda_fp16.h>
#include <cstdint>

#define BB   8
#define TT   2048
#define CIN  1024
#define HD   128
#define BT   (BB*TT)          // 16384 rows

typedef unsigned int u32;

// ---------------------------------------------------------------------------
// Device scratch (static globals: allocation-guard safe). fp16.
// ---------------------------------------------------------------------------
__device__ __align__(256) __half gQ[(size_t)BT * HD];
__device__ __align__(256) __half gK[(size_t)BT * HD];
__device__ __align__(256) __half gV[(size_t)BT * HD];
__device__ __align__(256) __half gW[3][HD * CIN];    // W^T fp16 [o][n][k]

// ---------------------------------------------------------------------------
// Helpers
// ---------------------------------------------------------------------------
__device__ __forceinline__ u32 pack_half2(float x, float y) {
    __half2 h = __floats2half2_rn(x, y);
    return *reinterpret_cast<u32*>(&h);
}
__device__ __forceinline__ void mma_f16(float* d, const u32* a, u32 b0, u32 b1) {
    asm volatile(
        "mma.sync.aligned.m16n8k16.row.col.f32.f16.f16.f32 "
        "{%0,%1,%2,%3}, {%4,%5,%6,%7}, {%8,%9}, {%0,%1,%2,%3};"
        : "+f"(d[0]), "+f"(d[1]), "+f"(d[2]), "+f"(d[3])
        : "r"(a[0]), "r"(a[1]), "r"(a[2]), "r"(a[3]), "r"(b0), "r"(b1));
}
__device__ __forceinline__ u32 smem_u32(const void* p) {
    u32 a;
    asm("{ .reg .u64 t; cvta.to.shared.u64 t, %1; cvt.u32.u64 %0, t; }"
        : "=r"(a) : "l"(p));
    return a;
}
__device__ __forceinline__ void ldsm4(u32 a, u32& r0, u32& r1, u32& r2, u32& r3) {
    asm volatile("ldmatrix.sync.aligned.m8n8.x4.shared.b16 {%0,%1,%2,%3}, [%4];"
                 : "=r"(r0), "=r"(r1), "=r"(r2), "=r"(r3) : "r"(a));
}
__device__ __forceinline__ void ldsm4t(u32 a, u32& r0, u32& r1, u32& r2, u32& r3) {
    asm volatile("ldmatrix.sync.aligned.m8n8.x4.trans.shared.b16 {%0,%1,%2,%3}, [%4];"
                 : "=r"(r0), "=r"(r1), "=r"(r2), "=r"(r3) : "r"(a));
}
#define CP16(dst, src) \
    asm volatile("cp.async.cg.shared.global [%0], [%1], 16;" \
                 :: "r"(dst), "l"(src) : "memory")
#define CP_COMMIT() asm volatile("cp.async.commit_group;" ::: "memory")
#define CP_WAIT(n)  asm volatile("cp.async.wait_group %0;" :: "n"(n) : "memory")

// ---------------------------------------------------------------------------
// Kernel A: transpose weights to fp16 via smem tile (coalesced both sides).
// ---------------------------------------------------------------------------
__global__ void convert_w(const float* __restrict__ Wq,
                          const float* __restrict__ Wk,
                          const float* __restrict__ Wv)
{
    __shared__ float tile[32][33];
    const int o  = blockIdx.z;
    const float* W = (o == 0) ? Wq : (o == 1 ? Wk : Wv);
    const int n0 = blockIdx.x * 32;
    const int k0 = blockIdx.y * 32;
    const int tx = threadIdx.x, ty = threadIdx.y;

    #pragma unroll
    for (int i = ty; i < 32; i += 8)
        tile[i][tx] = W[(size_t)(k0 + i) * HD + n0 + tx];
    __syncthreads();
    #pragma unroll
    for (int i = ty; i < 32; i += 8)
        gW[o][(size_t)(n0 + i) * CIN + k0 + tx] = __float2half_rn(tile[tx][i]);
}

// ---------------------------------------------------------------------------
// Kernel B: QKV GEMM. BM=128, BN=128, BK=32; 8 warps (4 wm x 2 wn).
// grid(3, 128): o fastest -> 3 CTAs with same m run together (X L2 reuse).
// fp16 single-term: Y = X16 @ W16.  1 MMA per slice. (unchanged)
// ---------------------------------------------------------------------------
#define GS 40   // smem k-stride (halves): 80B rows, 16B aligned, LDSM-conflict-free
#define GEMM_SMEM (2 * 128 * GS * 2)

__global__ __launch_bounds__(256) void qkv_mma(const float* __restrict__ X)
{
    extern __shared__ __half smg[];
    __half* Xs = smg;                 // [128][GS]
    __half* Ws = Xs + 128 * GS;       // [128 n][GS]
    const u32 Xs_b = smem_u32(Xs);
    const u32 Ws_b = smem_u32(Ws);

    const int t    = threadIdx.x;
    const int lane = t & 31;
    const int wrp  = t >> 5;
    const int wm   = wrp >> 1;
    const int wn   = wrp & 1;
    const int g    = lane >> 2;
    const int qd   = (lane & 3) << 1;
    const int j    = lane >> 3;
    const int lr   = lane & 7;
    const int o    = blockIdx.x;
    const size_t m0 = (size_t)blockIdx.y * 128;

    u32 ga_off[2];
    #pragma unroll
    for (int mf = 0; mf < 2; mf++)
        ga_off[mf] = (wm * 32 + mf * 16 + ((j & 1) << 3) + lr) * 80 + ((j >> 1) << 4);
    const u32 gb_off = (wn * 64 + ((j >> 1) << 3) + lr) * 80 + ((j & 1) << 4);

    const __half* Wg = gW[o];

    float acc[2][8][4];
    #pragma unroll
    for (int mf = 0; mf < 2; mf++)
        #pragma unroll
        for (int nf = 0; nf < 8; nf++)
            #pragma unroll
            for (int e = 0; e < 4; e++) acc[mf][nf][e] = 0.f;

    float4 xv[4];
    uint4  wv[2];
    const int xr  = t >> 3;
    const int xc  = (t & 7) << 2;
    const int wn_ = t >> 2;
    const int wc  = (t & 3) << 3;

    #pragma unroll
    for (int i = 0; i < 4; i++)
        xv[i] = *reinterpret_cast<const float4*>(X + (m0 + xr + i * 32) * CIN + xc);
    #pragma unroll
    for (int i = 0; i < 2; i++)
        wv[i] = *reinterpret_cast<const uint4*>(&Wg[(wn_ + i * 64) * CIN + wc]);

    for (int it = 0; it < 32; it++) {
        __syncthreads();
        #pragma unroll
        for (int i = 0; i < 4; i++) {
            const int r = xr + i * 32;
            *reinterpret_cast<u32*>(&Xs[r * GS + xc])     = pack_half2(xv[i].x, xv[i].y);
            *reinterpret_cast<u32*>(&Xs[r * GS + xc + 2]) = pack_half2(xv[i].z, xv[i].w);
        }
        #pragma unroll
        for (int i = 0; i < 2; i++)
            *reinterpret_cast<uint4*>(&Ws[(wn_ + i * 64) * GS + wc]) = wv[i];
        __syncthreads();

        if (it < 31) {
            const int k1 = (it + 1) * 32;
            #pragma unroll
            for (int i = 0; i < 4; i++)
                xv[i] = *reinterpret_cast<const float4*>(X + (m0 + xr + i * 32) * CIN + k1 + xc);
            #pragma unroll
            for (int i = 0; i < 2; i++)
                wv[i] = *reinterpret_cast<const uint4*>(&Wg[(wn_ + i * 64) * CIN + k1 + wc]);
        }

        #pragma unroll
        for (int ks = 0; ks < 2; ks++) {
            u32 ah[2][4];
            #pragma unroll
            for (int mf = 0; mf < 2; mf++)
                ldsm4(Xs_b + ga_off[mf] + ks * 32, ah[mf][0], ah[mf][1], ah[mf][2], ah[mf][3]);
            #pragma unroll
            for (int nf2 = 0; nf2 < 4; nf2++) {
                u32 b0, b1, b2, b3;
                ldsm4(Ws_b + gb_off + nf2 * (16 * 80) + ks * 32, b0, b1, b2, b3);
                #pragma unroll
                for (int mf = 0; mf < 2; mf++) {
                    mma_f16(acc[mf][2 * nf2],     ah[mf], b0, b1);
                    mma_f16(acc[mf][2 * nf2 + 1], ah[mf], b2, b3);
                }
            }
        }
    }

    // Epilogue: scale Q by 1/sqrt(1024), round to fp16 globals
    const float scale = (o == 0) ? 0.03125f : 1.0f;
    __half* G = (o == 0) ? gQ : (o == 1 ? gK : gV);
    #pragma unroll
    for (int mf = 0; mf < 2; mf++) {
        const size_t r = m0 + wm * 32 + mf * 16 + g;
        #pragma unroll
        for (int nf = 0; nf < 8; nf++) {
            const int col = wn * 64 + nf * 8 + qd;
            *reinterpret_cast<u32*>(&G[r * HD + col]) =
                pack_half2(acc[mf][nf][0] * scale, acc[mf][nf][1] * scale);
            *reinterpret_cast<u32*>(&G[(r + 8) * HD + col]) =
                pack_half2(acc[mf][nf][2] * scale, acc[mf][nf][3] * scale);
        }
    }
}

// ---------------------------------------------------------------------------
// Kernel C: causal flash attention, fp16, cross-tile pipelined.
// UNPAIRED grid(32, 8) = 256 CTAs, heavy-first: 2 CTAs/SM -> 2 warps/SMSP
// co-issue (latency hiding); work-stealing balances the causal skew.
// K double-buffered; V single-buffered issued at end of prior iter.
// ---------------------------------------------------------------------------
#define AST 136                      // smem row stride in halves (272 B)
#define TILE_B (64 * AST * 2)        // one 64x128 fp16 tile: 17408 B
#define ATTN_SMEM (3 * TILE_B)       // K0 K1 V = 52224 B

__device__ __forceinline__ void cp_tile64(u32 dst, const __half* src, int t)
{
    #pragma unroll
    for (int i = 0; i < 8; i++) {
        const int c   = t + i * 128;
        const int row = c >> 4;
        const int col = c & 15;
        CP16(dst + row * 272 + col * 16, src + row * 128 + col * 8);
    }
}

__global__ __launch_bounds__(128) void attn_kernel(float* __restrict__ out)
{
    extern __shared__ __half sma[];
    const u32 base = smem_u32(sma);
    const u32 K_s0 = base;
    const u32 K_s1 = base + TILE_B;
    const u32 V_b  = base + 2 * TILE_B;

    const int t    = threadIdx.x;
    const int lane = t & 31;
    const int w    = t >> 5;
    const int g    = lane >> 2;
    const int qd   = (lane & 3) << 1;
    const int j    = lane >> 3;
    const int lr   = lane & 7;
    const int b    = blockIdx.y;
    const int qt   = (int)gridDim.x - 1 - (int)blockIdx.x;   // heavy first
    const int i0   = qt * 64;

    // ldmatrix byte offsets (stride 272B)
    const u32 a_off  = (w * 16 + ((j & 1) << 3) + lr) * 272 + ((j >> 1) << 4);
    const u32 kb_off = (((j >> 1) << 3) + lr) * 272 + ((j & 1) << 4);
    const u32 vb_off = (((j & 1) << 3) + lr) * 272 + ((j >> 1) << 4);

    // ---- prologue: K(0)->s0, V(0)->V, Q staged through s1 ----
    cp_tile64(K_s0, gK + ((size_t)b * TT) * HD, t);
    cp_tile64(V_b,  gV + ((size_t)b * TT) * HD, t);
    cp_tile64(K_s1, gQ + ((size_t)b * TT + i0) * HD, t);
    CP_COMMIT();
    CP_WAIT(0);
    __syncthreads();

    u32 qh[8][4];
    #pragma unroll
    for (int ks = 0; ks < 8; ks++)
        ldsm4(K_s1 + a_off + ks * 32, qh[ks][0], qh[ks][1], qh[ks][2], qh[ks][3]);

    float O[16][4];
    #pragma unroll
    for (int nf = 0; nf < 16; nf++)
        #pragma unroll
        for (int e = 0; e < 4; e++) O[nf][e] = 0.f;
    float mrow[2] = {-1e30f, -1e30f};
    float lrow[2] = {0.f, 0.f};

    for (int jt = 0; jt <= qt; jt++) {
        const int stage = jt & 1;
        const u32 kh = stage ? K_s1 : K_s0;

        CP_WAIT(1);          // K(jt) complete (V(jt) may still be in flight)
        __syncthreads();

        // prefetch K(jt+1) into the other stage
        if (jt < qt)
            cp_tile64(stage ? K_s0 : K_s1,
                      gK + ((size_t)b * TT + (jt + 1) * 64) * HD, t);
        CP_COMMIT();         // empty group on last iter keeps cadence uniform

        // ---- S = Q K^T ----
        float s[8][4];
        #pragma unroll
        for (int nf = 0; nf < 8; nf++)
            #pragma unroll
            for (int e = 0; e < 4; e++) s[nf][e] = 0.f;

        #pragma unroll
        for (int ks = 0; ks < 8; ks++) {
            #pragma unroll
            for (int nf2 = 0; nf2 < 4; nf2++) {
                u32 b0, b1, b2, b3;
                ldsm4(kh + kb_off + nf2 * (16 * 272) + ks * 32, b0, b1, b2, b3);
                mma_f16(s[2 * nf2],     qh[ks], b0, b1);
                mma_f16(s[2 * nf2 + 1], qh[ks], b2, b3);
            }
        }

        // ---- causal mask on diagonal tile ----
        if (jt == qt) {
            #pragma unroll
            for (int nf = 0; nf < 8; nf++) {
                const int c0 = nf * 8 + qd;
                const int r0 = w * 16 + g;
                if (c0     > r0)     s[nf][0] = -1e30f;
                if (c0 + 1 > r0)     s[nf][1] = -1e30f;
                if (c0     > r0 + 8) s[nf][2] = -1e30f;
                if (c0 + 1 > r0 + 8) s[nf][3] = -1e30f;
            }
        }

        // ---- online softmax ----
        float mx0 = -1e30f, mx1 = -1e30f;
        #pragma unroll
        for (int nf = 0; nf < 8; nf++) {
            mx0 = fmaxf(mx0, fmaxf(s[nf][0], s[nf][1]));
            mx1 = fmaxf(mx1, fmaxf(s[nf][2], s[nf][3]));
        }
        mx0 = fmaxf(mx0, __shfl_xor_sync(0xffffffffu, mx0, 1));
        mx0 = fmaxf(mx0, __shfl_xor_sync(0xffffffffu, mx0, 2));
        mx1 = fmaxf(mx1, __shfl_xor_sync(0xffffffffu, mx1, 1));
        mx1 = fmaxf(mx1, __shfl_xor_sync(0xffffffffu, mx1, 2));
        const float mn0 = fmaxf(mrow[0], mx0);
        const float mn1 = fmaxf(mrow[1], mx1);
        const float a0  = __expf(mrow[0] - mn0);
        const float a1  = __expf(mrow[1] - mn1);
        mrow[0] = mn0; mrow[1] = mn1;

        float sum0 = 0.f, sum1 = 0.f;
        #pragma unroll
        for (int nf = 0; nf < 8; nf++) {
            s[nf][0] = __expf(s[nf][0] - mn0);
            s[nf][1] = __expf(s[nf][1] - mn0);
            s[nf][2] = __expf(s[nf][2] - mn1);
            s[nf][3] = __expf(s[nf][3] - mn1);
            sum0 += s[nf][0] + s[nf][1];
            sum1 += s[nf][2] + s[nf][3];
        }
        sum0 += __shfl_xor_sync(0xffffffffu, sum0, 1);
        sum0 += __shfl_xor_sync(0xffffffffu, sum0, 2);
        sum1 += __shfl_xor_sync(0xffffffffu, sum1, 1);
        sum1 += __shfl_xor_sync(0xffffffffu, sum1, 2);
        lrow[0] = lrow[0] * a0 + sum0;
        lrow[1] = lrow[1] * a1 + sum1;

        #pragma unroll
        for (int nf = 0; nf < 16; nf++) {
            O[nf][0] *= a0; O[nf][1] *= a0;
            O[nf][2] *= a1; O[nf][3] *= a1;
        }

        CP_WAIT(1);          // V(jt) complete (K(jt+1) may still be in flight)
        __syncthreads();

        // ---- O += P V : P rounded to fp16, V frags via ldmatrix.trans ----
        #pragma unroll
        for (int ks = 0; ks < 4; ks++) {
            u32 ph[4];
            ph[0] = pack_half2(s[2 * ks][0],     s[2 * ks][1]);
            ph[1] = pack_half2(s[2 * ks][2],     s[2 * ks][3]);
            ph[2] = pack_half2(s[2 * ks + 1][0], s[2 * ks + 1][1]);
            ph[3] = pack_half2(s[2 * ks + 1][2], s[2 * ks + 1][3]);
            #pragma unroll
            for (int nf2 = 0; nf2 < 8; nf2++) {
                u32 b0, b1, b2, b3;
                ldsm4t(V_b + vb_off + ks * (16 * 272) + nf2 * 32, b0, b1, b2, b3);
                mma_f16(O[2 * nf2],     ph, b0, b1);
                mma_f16(O[2 * nf2 + 1], ph, b2, b3);
            }
        }

        __syncthreads();     // all warps done reading V(jt) before overwrite
        if (jt < qt)
            cp_tile64(V_b, gV + ((size_t)b * TT + (jt + 1) * 64) * HD, t);
        CP_COMMIT();
    }

    // ---- epilogue: normalize + store fp32 ----
    const float inv0 = 1.0f / lrow[0];
    const float inv1 = 1.0f / lrow[1];
    const size_t r0 = (size_t)b * TT + i0 + w * 16 + g;
    #pragma unroll
    for (int nf = 0; nf < 16; nf++) {
        const int col = nf * 8 + qd;
        float2 v0 = make_float2(O[nf][0] * inv0, O[nf][1] * inv0);
        float2 v1 = make_float2(O[nf][2] * inv1, O[nf][3] * inv1);
        *reinterpret_cast<float2*>(out + r0 * HD + col)       = v0;
        *reinterpret_cast<float2*>(out + (r0 + 8) * HD + col) = v1;
    }
}

// ---------------------------------------------------------------------------
extern "C" void kernel_launch(void* const* d_in, const int* in_sizes, int n_in,
                              void* d_out, int out_size)
{
    const float* X  = (const float*)d_in[0];   // [8,2048,1024]
    const float* Wq = (const float*)d_in[1];   // [1024,128]
    const float* Wk = (const float*)d_in[2];
    const float* Wv = (const float*)d_in[3];
    float* out = (float*)d_out;                // [8,2048,128]
    (void)in_sizes; (void)n_in; (void)out_size;

    cudaFuncSetAttribute(qkv_mma,
        cudaFuncAttributeMaxDynamicSharedMemorySize, GEMM_SMEM);
    cudaFuncSetAttribute(attn_kernel,
        cudaFuncAttributeMaxDynamicSharedMemorySize, ATTN_SMEM);

    convert_w<<<dim3(HD / 32, CIN / 32, 3), dim3(32, 8)>>>(Wq, Wk, Wv);
    qkv_mma<<<dim3(3, BT / 128), 256, GEMM_SMEM>>>(X);
    attn_kernel<<<dim3(TT / 64, BB), 128, ATTN_SMEM>>>(out);
}

// round 12
// speedup vs baseline: 1.2741x; 1.2741x over previous
#include <cuda_runtime.h>
#include <cuda_fp16.h>
#include <cstdint>

#define BB   8
#define TT   2048
#define CIN  1024
#define HD   128
#define BT   (BB*TT)          // 16384 rows

typedef unsigned int u32;

// ---------------------------------------------------------------------------
// Device scratch (static globals: allocation-guard safe). fp16.
// ---------------------------------------------------------------------------
__device__ __align__(256) __half gQ[(size_t)BT * HD];
__device__ __align__(256) __half gK[(size_t)BT * HD];
__device__ __align__(256) __half gV[(size_t)BT * HD];

// ---------------------------------------------------------------------------
// Helpers
// ---------------------------------------------------------------------------
__device__ __forceinline__ u32 pack_half2(float x, float y) {
    __half2 h = __floats2half2_rn(x, y);
    return *reinterpret_cast<u32*>(&h);
}
__device__ __forceinline__ void mma_f16(float* d, const u32* a, u32 b0, u32 b1) {
    asm volatile(
        "mma.sync.aligned.m16n8k16.row.col.f32.f16.f16.f32 "
        "{%0,%1,%2,%3}, {%4,%5,%6,%7}, {%8,%9}, {%0,%1,%2,%3};"
        : "+f"(d[0]), "+f"(d[1]), "+f"(d[2]), "+f"(d[3])
        : "r"(a[0]), "r"(a[1]), "r"(a[2]), "r"(a[3]), "r"(b0), "r"(b1));
}
__device__ __forceinline__ u32 smem_u32(const void* p) {
    u32 a;
    asm("{ .reg .u64 t; cvta.to.shared.u64 t, %1; cvt.u32.u64 %0, t; }"
        : "=r"(a) : "l"(p));
    return a;
}
__device__ __forceinline__ void ldsm4(u32 a, u32& r0, u32& r1, u32& r2, u32& r3) {
    asm volatile("ldmatrix.sync.aligned.m8n8.x4.shared.b16 {%0,%1,%2,%3}, [%4];"
                 : "=r"(r0), "=r"(r1), "=r"(r2), "=r"(r3) : "r"(a));
}
__device__ __forceinline__ void ldsm4t(u32 a, u32& r0, u32& r1, u32& r2, u32& r3) {
    asm volatile("ldmatrix.sync.aligned.m8n8.x4.trans.shared.b16 {%0,%1,%2,%3}, [%4];"
                 : "=r"(r0), "=r"(r1), "=r"(r2), "=r"(r3) : "r"(a));
}
#define CP16(dst, src) \
    asm volatile("cp.async.cg.shared.global [%0], [%1], 16;" \
                 :: "r"(dst), "l"(src) : "memory")
#define CP_COMMIT() asm volatile("cp.async.commit_group;" ::: "memory")
#define CP_WAIT(n)  asm volatile("cp.async.wait_group %0;" :: "n"(n) : "memory")
#define BAR_GRP(id) asm volatile("bar.sync %0, 128;" :: "r"(id) : "memory")

// ---------------------------------------------------------------------------
// Kernel B: QKV GEMM with inline W fp32->fp16 conversion.
// BM=128, BN=128, BK=32; 8 warps (4 wm x 2 wn). grid(3, 128), o fastest.
// X: fp16 smem [m][k] (80B rows), A-frags ldmatrix.
// W: fp16 smem [k][n] (272B rows), B-frags ldmatrix.trans (validated pattern).
// ---------------------------------------------------------------------------
#define GS  40                            // X smem k-stride (halves)
#define WST 136                           // W smem n-stride (halves)
#define GEMM_SMEM ((128 * GS + 32 * WST) * 2)

__global__ __launch_bounds__(256) void qkv_mma(const float* __restrict__ X,
                                               const float* __restrict__ Wq,
                                               const float* __restrict__ Wk,
                                               const float* __restrict__ Wv)
{
    extern __shared__ __half smg[];
    __half* Xs = smg;                     // [128][GS]
    __half* Ws = Xs + 128 * GS;           // [32 k][WST n]
    const u32 Xs_b = smem_u32(Xs);
    const u32 Ws_b = smem_u32(Ws);

    const int t    = threadIdx.x;
    const int lane = t & 31;
    const int wrp  = t >> 5;
    const int wm   = wrp >> 1;
    const int wn   = wrp & 1;
    const int g    = lane >> 2;
    const int qd   = (lane & 3) << 1;
    const int j    = lane >> 3;
    const int lr   = lane & 7;
    const int o    = blockIdx.x;
    const size_t m0 = (size_t)blockIdx.y * 128;

    u32 ga_off[2];
    #pragma unroll
    for (int mf = 0; mf < 2; mf++)
        ga_off[mf] = (wm * 32 + mf * 16 + ((j & 1) << 3) + lr) * 80 + ((j >> 1) << 4);
    // B-frags via ldsm4t on [k][n] layout (272B stride), warp n-offset wn*64
    const u32 gbT_off = (((j & 1) << 3) + lr) * 272 + ((j >> 1) << 4) + wn * 128;

    const float* Wg = (o == 0) ? Wq : (o == 1 ? Wk : Wv);

    float acc[2][8][4];
    #pragma unroll
    for (int mf = 0; mf < 2; mf++)
        #pragma unroll
        for (int nf = 0; nf < 8; nf++)
            #pragma unroll
            for (int e = 0; e < 4; e++) acc[mf][nf][e] = 0.f;

    float4 xv[4], wf[4];
    const int xr  = t >> 3;               // X row base
    const int xc  = (t & 7) << 2;         // X col (floats)
    const int wr  = t >> 5;               // W k-row base (0..7)
    const int wc4 = (t & 31) << 2;        // W n col (floats)

    #pragma unroll
    for (int i = 0; i < 4; i++) {
        xv[i] = *reinterpret_cast<const float4*>(X + (m0 + xr + i * 32) * CIN + xc);
        wf[i] = *reinterpret_cast<const float4*>(Wg + (size_t)(wr + i * 8) * HD + wc4);
    }

    for (int it = 0; it < 32; it++) {
        __syncthreads();
        #pragma unroll
        for (int i = 0; i < 4; i++) {
            const int r = xr + i * 32;
            *reinterpret_cast<u32*>(&Xs[r * GS + xc])     = pack_half2(xv[i].x, xv[i].y);
            *reinterpret_cast<u32*>(&Xs[r * GS + xc + 2]) = pack_half2(xv[i].z, xv[i].w);
            const int kr = wr + i * 8;
            *reinterpret_cast<u32*>(&Ws[kr * WST + wc4])     = pack_half2(wf[i].x, wf[i].y);
            *reinterpret_cast<u32*>(&Ws[kr * WST + wc4 + 2]) = pack_half2(wf[i].z, wf[i].w);
        }
        __syncthreads();

        if (it < 31) {
            const int k1 = (it + 1) * 32;
            #pragma unroll
            for (int i = 0; i < 4; i++) {
                xv[i] = *reinterpret_cast<const float4*>(X + (m0 + xr + i * 32) * CIN + k1 + xc);
                wf[i] = *reinterpret_cast<const float4*>(Wg + (size_t)(k1 + wr + i * 8) * HD + wc4);
            }
        }

        #pragma unroll
        for (int ks = 0; ks < 2; ks++) {
            u32 ah[2][4];
            #pragma unroll
            for (int mf = 0; mf < 2; mf++)
                ldsm4(Xs_b + ga_off[mf] + ks * 32, ah[mf][0], ah[mf][1], ah[mf][2], ah[mf][3]);
            #pragma unroll
            for (int nf2 = 0; nf2 < 4; nf2++) {
                u32 b0, b1, b2, b3;
                ldsm4t(Ws_b + gbT_off + ks * (16 * 272) + nf2 * 32, b0, b1, b2, b3);
                #pragma unroll
                for (int mf = 0; mf < 2; mf++) {
                    mma_f16(acc[mf][2 * nf2],     ah[mf], b0, b1);
                    mma_f16(acc[mf][2 * nf2 + 1], ah[mf], b2, b3);
                }
            }
        }
    }

    // Epilogue: scale Q by 1/sqrt(1024), round to fp16 globals
    const float scale = (o == 0) ? 0.03125f : 1.0f;
    __half* G = (o == 0) ? gQ : (o == 1 ? gK : gV);
    #pragma unroll
    for (int mf = 0; mf < 2; mf++) {
        const size_t r = m0 + wm * 32 + mf * 16 + g;
        #pragma unroll
        for (int nf = 0; nf < 8; nf++) {
            const int col = wn * 64 + nf * 8 + qd;
            *reinterpret_cast<u32*>(&G[r * HD + col]) =
                pack_half2(acc[mf][nf][0] * scale, acc[mf][nf][1] * scale);
            *reinterpret_cast<u32*>(&G[(r + 8) * HD + col]) =
                pack_half2(acc[mf][nf][2] * scale, acc[mf][nf][3] * scale);
        }
    }
}

// ---------------------------------------------------------------------------
// Kernel C: causal flash attention, fp16, PAIRED grid + split-KV warp groups.
// grid(16, 8), 256 threads. CTA processes q-tiles {31-x, x} sequentially.
// Warp-group A (warps 0-3) handles even KV tiles, group B (4-7) odd tiles;
// each group has its own K double-buffer + V buffer and its own (m,l,O);
// one smem merge at the end (online softmax is associative).
// 128 CTAs -> 1/SM (perfect balance) with 2 warps/SMSP (latency hiding).
// ---------------------------------------------------------------------------
#define AST 136                      // smem row stride in halves (272 B)
#define TILE_B (64 * AST * 2)        // one 64x128 fp16 tile: 17408 B
#define ATTN_SMEM (6 * TILE_B)       // per group: K0 K1 V -> 104448 B total

__device__ __forceinline__ void cp_tile64(u32 dst, const __half* src, int tg)
{
    #pragma unroll
    for (int i = 0; i < 8; i++) {         // 128 threads x 8 = 1024 chunks of 16B
        const int c   = tg + i * 128;
        const int row = c >> 4;           // 0..63
        const int col = c & 15;
        CP16(dst + row * 272 + col * 16, src + row * 128 + col * 8);
    }
}

__global__ __launch_bounds__(256) void attn_kernel(float* __restrict__ out)
{
    extern __shared__ __half sma[];
    const u32 base = smem_u32(sma);

    const int t    = threadIdx.x;
    const int lane = t & 31;
    const int warp = t >> 5;
    const int wg   = warp >> 2;           // 0 = group A (even jt), 1 = B (odd jt)
    const int w4   = warp & 3;            // warp within group -> q-rows w4*16..+15
    const int tg   = t & 127;             // thread id within group
    const int g    = lane >> 2;
    const int qd   = (lane & 3) << 1;
    const int j    = lane >> 3;
    const int lr   = lane & 7;
    const int b    = blockIdx.y;

    const u32 gbase = base + (u32)wg * 3 * TILE_B;
    const u32 K_s0 = gbase, K_s1 = gbase + TILE_B, V_b = gbase + 2 * TILE_B;

    const u32 a_off  = (w4 * 16 + ((j & 1) << 3) + lr) * 272 + ((j >> 1) << 4);
    const u32 kb_off = (((j >> 1) << 3) + lr) * 272 + ((j & 1) << 4);
    const u32 vb_off = (((j & 1) << 3) + lr) * 272 + ((j >> 1) << 4);

    #pragma unroll 1
    for (int half = 0; half < 2; half++) {
        const int qt = (half == 0) ? (31 - (int)blockIdx.x) : (int)blockIdx.x;
        const int i0 = qt * 64;
        const int n_g = (qt >= wg) ? (((qt - wg) >> 1) + 1) : 0;

        float O[16][4];
        #pragma unroll
        for (int nf = 0; nf < 16; nf++)
            #pragma unroll
            for (int e = 0; e < 4; e++) O[nf][e] = 0.f;
        float mrow[2] = {-1e30f, -1e30f};
        float lrow[2] = {0.f, 0.f};

        if (n_g > 0) {
            // ---- prologue: K(wg)->s0, V(wg)->V, Q staged through s1 ----
            cp_tile64(K_s0, gK + ((size_t)b * TT + wg * 64) * HD, tg);
            cp_tile64(V_b,  gV + ((size_t)b * TT + wg * 64) * HD, tg);
            cp_tile64(K_s1, gQ + ((size_t)b * TT + i0) * HD, tg);
            CP_COMMIT();
            CP_WAIT(0);
            BAR_GRP(wg + 1);

            u32 qh[8][4];
            #pragma unroll
            for (int ks = 0; ks < 8; ks++)
                ldsm4(K_s1 + a_off + ks * 32, qh[ks][0], qh[ks][1], qh[ks][2], qh[ks][3]);

            for (int i = 0; i < n_g; i++) {
                const int jt = wg + 2 * i;
                const int stage = i & 1;
                const u32 kh = stage ? K_s1 : K_s0;

                CP_WAIT(1);              // K(i) complete (V(i) may be in flight)
                BAR_GRP(wg + 1);

                if (i + 1 < n_g)
                    cp_tile64(stage ? K_s0 : K_s1,
                              gK + ((size_t)b * TT + (jt + 2) * 64) * HD, tg);
                CP_COMMIT();             // empty group keeps wait cadence uniform

                // ---- S = Q K^T ----
                float s[8][4];
                #pragma unroll
                for (int nf = 0; nf < 8; nf++)
                    #pragma unroll
                    for (int e = 0; e < 4; e++) s[nf][e] = 0.f;

                #pragma unroll
                for (int ks = 0; ks < 8; ks++) {
                    #pragma unroll
                    for (int nf2 = 0; nf2 < 4; nf2++) {
                        u32 b0, b1, b2, b3;
                        ldsm4(kh + kb_off + nf2 * (16 * 272) + ks * 32, b0, b1, b2, b3);
                        mma_f16(s[2 * nf2],     qh[ks], b0, b1);
                        mma_f16(s[2 * nf2 + 1], qh[ks], b2, b3);
                    }
                }

                // ---- causal mask on diagonal tile ----
                if (jt == qt) {
                    #pragma unroll
                    for (int nf = 0; nf < 8; nf++) {
                        const int c0 = nf * 8 + qd;
                        const int r0 = w4 * 16 + g;
                        if (c0     > r0)     s[nf][0] = -1e30f;
                        if (c0 + 1 > r0)     s[nf][1] = -1e30f;
                        if (c0     > r0 + 8) s[nf][2] = -1e30f;
                        if (c0 + 1 > r0 + 8) s[nf][3] = -1e30f;
                    }
                }

                // ---- online softmax ----
                float mx0 = -1e30f, mx1 = -1e30f;
                #pragma unroll
                for (int nf = 0; nf < 8; nf++) {
                    mx0 = fmaxf(mx0, fmaxf(s[nf][0], s[nf][1]));
                    mx1 = fmaxf(mx1, fmaxf(s[nf][2], s[nf][3]));
                }
                mx0 = fmaxf(mx0, __shfl_xor_sync(0xffffffffu, mx0, 1));
                mx0 = fmaxf(mx0, __shfl_xor_sync(0xffffffffu, mx0, 2));
                mx1 = fmaxf(mx1, __shfl_xor_sync(0xffffffffu, mx1, 1));
                mx1 = fmaxf(mx1, __shfl_xor_sync(0xffffffffu, mx1, 2));
                const float mn0 = fmaxf(mrow[0], mx0);
                const float mn1 = fmaxf(mrow[1], mx1);
                const float a0  = __expf(mrow[0] - mn0);
                const float a1  = __expf(mrow[1] - mn1);
                mrow[0] = mn0; mrow[1] = mn1;

                float sum0 = 0.f, sum1 = 0.f;
                #pragma unroll
                for (int nf = 0; nf < 8; nf++) {
                    s[nf][0] = __expf(s[nf][0] - mn0);
                    s[nf][1] = __expf(s[nf][1] - mn0);
                    s[nf][2] = __expf(s[nf][2] - mn1);
                    s[nf][3] = __expf(s[nf][3] - mn1);
                    sum0 += s[nf][0] + s[nf][1];
                    sum1 += s[nf][2] + s[nf][3];
                }
                sum0 += __shfl_xor_sync(0xffffffffu, sum0, 1);
                sum0 += __shfl_xor_sync(0xffffffffu, sum0, 2);
                sum1 += __shfl_xor_sync(0xffffffffu, sum1, 1);
                sum1 += __shfl_xor_sync(0xffffffffu, sum1, 2);
                lrow[0] = lrow[0] * a0 + sum0;
                lrow[1] = lrow[1] * a1 + sum1;

                #pragma unroll
                for (int nf = 0; nf < 16; nf++) {
                    O[nf][0] *= a0; O[nf][1] *= a0;
                    O[nf][2] *= a1; O[nf][3] *= a1;
                }

                CP_WAIT(1);              // V(i) complete
                BAR_GRP(wg + 1);

                // ---- O += P V ----
                #pragma unroll
                for (int ks = 0; ks < 4; ks++) {
                    u32 ph[4];
                    ph[0] = pack_half2(s[2 * ks][0],     s[2 * ks][1]);
                    ph[1] = pack_half2(s[2 * ks][2],     s[2 * ks][3]);
                    ph[2] = pack_half2(s[2 * ks + 1][0], s[2 * ks + 1][1]);
                    ph[3] = pack_half2(s[2 * ks + 1][2], s[2 * ks + 1][3]);
                    #pragma unroll
                    for (int nf2 = 0; nf2 < 8; nf2++) {
                        u32 b0, b1, b2, b3;
                        ldsm4t(V_b + vb_off + ks * (16 * 272) + nf2 * 32, b0, b1, b2, b3);
                        mma_f16(O[2 * nf2],     ph, b0, b1);
                        mma_f16(O[2 * nf2 + 1], ph, b2, b3);
                    }
                }

                BAR_GRP(wg + 1);         // group done reading V before overwrite
                if (i + 1 < n_g)
                    cp_tile64(V_b, gV + ((size_t)b * TT + (jt + 2) * 64) * HD, tg);
                CP_COMMIT();
            }
            CP_WAIT(0);
        }

        // ---- merge group B partials into A, then A stores ----
        float* ex = reinterpret_cast<float*>(reinterpret_cast<char*>(sma) + 3 * TILE_B);
        if (wg == 1) {
            float* p = ex + tg * 68;
            #pragma unroll
            for (int nf = 0; nf < 16; nf++) {
                p[nf * 4 + 0] = O[nf][0]; p[nf * 4 + 1] = O[nf][1];
                p[nf * 4 + 2] = O[nf][2]; p[nf * 4 + 3] = O[nf][3];
            }
            p[64] = mrow[0]; p[65] = mrow[1];
            p[66] = lrow[0]; p[67] = lrow[1];
        }
        __syncthreads();
        if (wg == 0) {
            const float* p = ex + tg * 68;
            const float mB0 = p[64], mB1 = p[65], lB0 = p[66], lB1 = p[67];
            const float m0 = fmaxf(mrow[0], mB0);
            const float m1 = fmaxf(mrow[1], mB1);
            const float aA0 = __expf(mrow[0] - m0), aB0 = __expf(mB0 - m0);
            const float aA1 = __expf(mrow[1] - m1), aB1 = __expf(mB1 - m1);
            const float inv0 = 1.0f / (lrow[0] * aA0 + lB0 * aB0);
            const float inv1 = 1.0f / (lrow[1] * aA1 + lB1 * aB1);
            const size_t r0 = (size_t)b * TT + i0 + w4 * 16 + g;
            #pragma unroll
            for (int nf = 0; nf < 16; nf++) {
                const int col = nf * 8 + qd;
                float2 v0 = make_float2(
                    (O[nf][0] * aA0 + p[nf * 4 + 0] * aB0) * inv0,
                    (O[nf][1] * aA0 + p[nf * 4 + 1] * aB0) * inv0);
                float2 v1 = make_float2(
                    (O[nf][2] * aA1 + p[nf * 4 + 2] * aB1) * inv1,
                    (O[nf][3] * aA1 + p[nf * 4 + 3] * aB1) * inv1);
                *reinterpret_cast<float2*>(out + r0 * HD + col)       = v0;
                *reinterpret_cast<float2*>(out + (r0 + 8) * HD + col) = v1;
            }
        }
        __syncthreads();     // protect exchange area before next half's prologue
    }
}

// ---------------------------------------------------------------------------
extern "C" void kernel_launch(void* const* d_in, const int* in_sizes, int n_in,
                              void* d_out, int out_size)
{
    const float* X  = (const float*)d_in[0];   // [8,2048,1024]
    const float* Wq = (const float*)d_in[1];   // [1024,128]
    const float* Wk = (const float*)d_in[2];
    const float* Wv = (const float*)d_in[3];
    float* out = (float*)d_out;                // [8,2048,128]
    (void)in_sizes; (void)n_in; (void)out_size;

    cudaFuncSetAttribute(qkv_mma,
        cudaFuncAttributeMaxDynamicSharedMemorySize, GEMM_SMEM);
    cudaFuncSetAttribute(attn_kernel,
        cudaFuncAttributeMaxDynamicSharedMemorySize, ATTN_SMEM);

    qkv_mma<<<dim3(3, BT / 128), 256, GEMM_SMEM>>>(X, Wq, Wk, Wv);
    attn_kernel<<<dim3(16, BB), 256, ATTN_SMEM>>>(out);
}

// round 14
// speedup vs baseline: 1.4723x; 1.1555x over previous
#include <cuda_runtime.h>
#include <cuda_fp16.h>
#include <cstdint>

#define BB   8
#define TT   2048
#define CIN  1024
#define HD   128
#define BT   (BB*TT)          // 16384 rows

typedef unsigned int u32;

// ---------------------------------------------------------------------------
// Device scratch (static globals: allocation-guard safe). fp16.
// ---------------------------------------------------------------------------
__device__ __align__(256) __half gQ[(size_t)BT * HD];
__device__ __align__(256) __half gK[(size_t)BT * HD];
__device__ __align__(256) __half gV[(size_t)BT * HD];
__device__ __align__(256) __half gWc[3 * CIN * HD];   // fp16 W, [o][k][n]

// ---------------------------------------------------------------------------
// Helpers
// ---------------------------------------------------------------------------
__device__ __forceinline__ u32 pack_half2(float x, float y) {
    __half2 h = __floats2half2_rn(x, y);
    return *reinterpret_cast<u32*>(&h);
}
__device__ __forceinline__ void mma_f16(float* d, const u32* a, u32 b0, u32 b1) {
    asm volatile(
        "mma.sync.aligned.m16n8k16.row.col.f32.f16.f16.f32 "
        "{%0,%1,%2,%3}, {%4,%5,%6,%7}, {%8,%9}, {%0,%1,%2,%3};"
        : "+f"(d[0]), "+f"(d[1]), "+f"(d[2]), "+f"(d[3])
        : "r"(a[0]), "r"(a[1]), "r"(a[2]), "r"(a[3]), "r"(b0), "r"(b1));
}
__device__ __forceinline__ u32 smem_u32(const void* p) {
    u32 a;
    asm("{ .reg .u64 t; cvta.to.shared.u64 t, %1; cvt.u32.u64 %0, t; }"
        : "=r"(a) : "l"(p));
    return a;
}
__device__ __forceinline__ void ldsm4(u32 a, u32& r0, u32& r1, u32& r2, u32& r3) {
    asm volatile("ldmatrix.sync.aligned.m8n8.x4.shared.b16 {%0,%1,%2,%3}, [%4];"
                 : "=r"(r0), "=r"(r1), "=r"(r2), "=r"(r3) : "r"(a));
}
__device__ __forceinline__ void ldsm4t(u32 a, u32& r0, u32& r1, u32& r2, u32& r3) {
    asm volatile("ldmatrix.sync.aligned.m8n8.x4.trans.shared.b16 {%0,%1,%2,%3}, [%4];"
                 : "=r"(r0), "=r"(r1), "=r"(r2), "=r"(r3) : "r"(a));
}
#define CP16(dst, src) \
    asm volatile("cp.async.cg.shared.global [%0], [%1], 16;" \
                 :: "r"(dst), "l"(src) : "memory")
#define CP_COMMIT() asm volatile("cp.async.commit_group;" ::: "memory")
#define CP_WAIT(n)  asm volatile("cp.async.wait_group %0;" :: "n"(n) : "memory")
#define BAR_GRP(id) asm volatile("bar.sync %0, 128;" :: "r"(id) : "memory")

// ---------------------------------------------------------------------------
// Kernel A: elementwise W fp32 -> fp16, [o][k][n] (no transpose; 8 elems/thr).
// ---------------------------------------------------------------------------
__global__ __launch_bounds__(256) void convert_w(const float* __restrict__ Wq,
                                                 const float* __restrict__ Wk,
                                                 const float* __restrict__ Wv)
{
    const size_t base = ((size_t)blockIdx.x * 256 + threadIdx.x) * 8;
    const int o = (int)(base >> 17);
    const int r = (int)(base & 131071);
    const float* W = (o == 0) ? Wq : (o == 1 ? Wk : Wv);
    float4 a = *reinterpret_cast<const float4*>(W + r);
    float4 b = *reinterpret_cast<const float4*>(W + r + 4);
    uint4 v;
    v.x = pack_half2(a.x, a.y); v.y = pack_half2(a.z, a.w);
    v.z = pack_half2(b.x, b.y); v.w = pack_half2(b.z, b.w);
    *reinterpret_cast<uint4*>(gWc + (size_t)o * (CIN * HD) + r) = v;
}

// ---------------------------------------------------------------------------
// Kernel B: FUSED QKV GEMM — one CTA computes Q,K,V (N=384) for 64 M-rows.
// BM=64, BK=32; 8 warps = 2 wm x 4 wh (each warp: 32 m-rows x 96 n-cols
// -> acc[2][12][4] = exactly 96 floats/thread, full coverage).
// X: fp32 LDG reg-prefetch -> fp16 smem [m][k] (80B rows), A-frags ldmatrix.
// W: fp16 cp.async double-buffered smem [k][384n] (784B rows), B ldmatrix.trans.
// grid(256): X loaded once; W stages stream from L2 (1.5MB resident).
// ---------------------------------------------------------------------------
#define GS   40                           // X smem k-stride (halves)
#define WST2 392                          // W smem n-stride (halves), 784 B
#define WSTG (32 * WST2)                  // halves per W stage
#define GEMM_SMEM ((64 * GS + 2 * WSTG) * 2)

__global__ __launch_bounds__(256) void qkv_mma(const float* __restrict__ X)
{
    extern __shared__ __half smg[];
    __half* Xs = smg;                     // [64][GS]
    const u32 Xs_b = smem_u32(Xs);
    const u32 Ws_b = smem_u32(Xs + 64 * GS);    // two stages of [32][WST2]

    const int t    = threadIdx.x;
    const int lane = t & 31;
    const int wrp  = t >> 5;
    const int wm   = wrp & 1;             // m-group: rows wm*32..+31
    const int wh   = wrp >> 1;            // n-quarter: cols wh*96..+95
    const int g    = lane >> 2;
    const int qd   = (lane & 3) << 1;
    const int j    = lane >> 3;
    const int lr   = lane & 7;
    const size_t m0 = (size_t)blockIdx.x * 64;

    u32 ga_off[2];
    #pragma unroll
    for (int mf = 0; mf < 2; mf++)
        ga_off[mf] = (wm * 32 + mf * 16 + ((j & 1) << 3) + lr) * 80 + ((j >> 1) << 4);
    const u32 bT_off = (((j & 1) << 3) + lr) * 784 + ((j >> 1) << 4) + wh * 192;

    float acc[2][12][4];
    #pragma unroll
    for (int mf = 0; mf < 2; mf++)
        #pragma unroll
        for (int nf = 0; nf < 12; nf++)
            #pragma unroll
            for (int e = 0; e < 4; e++) acc[mf][nf][e] = 0.f;

    float4 xv[2];
    const int xr = t >> 3;                // X row base (0..31)
    const int xc = (t & 7) << 2;          // X col (floats)
    const int wk0 = t >> 4, wn0 = t & 15; // W cp.async indices

    // ---- prologue: X(0) into regs, W(0) into stage 0 ----
    #pragma unroll
    for (int i = 0; i < 2; i++)
        xv[i] = *reinterpret_cast<const float4*>(X + (m0 + xr + i * 32) * CIN + xc);
    #pragma unroll
    for (int o = 0; o < 3; o++)
        #pragma unroll
        for (int jj = 0; jj < 2; jj++) {
            const int k = wk0 + jj * 16, n16 = wn0;
            CP16(Ws_b + k * 784 + o * 256 + n16 * 16,
                 gWc + (size_t)o * (CIN * HD) + (size_t)k * HD + n16 * 8);
        }
    CP_COMMIT();

    for (int it = 0; it < 32; it++) {
        __syncthreads();                  // prior iter done reading Xs
        #pragma unroll
        for (int i = 0; i < 2; i++) {
            const int r = xr + i * 32;
            *reinterpret_cast<u32*>(&Xs[r * GS + xc])     = pack_half2(xv[i].x, xv[i].y);
            *reinterpret_cast<u32*>(&Xs[r * GS + xc + 2]) = pack_half2(xv[i].z, xv[i].w);
        }
        if (it < 31) {
            const int k1 = (it + 1) * 32;
            #pragma unroll
            for (int i = 0; i < 2; i++)
                xv[i] = *reinterpret_cast<const float4*>(X + (m0 + xr + i * 32) * CIN + k1 + xc);
            const u32 dstb = Ws_b + ((it + 1) & 1) * (WSTG * 2);
            #pragma unroll
            for (int o = 0; o < 3; o++)
                #pragma unroll
                for (int jj = 0; jj < 2; jj++) {
                    const int k = wk0 + jj * 16, n16 = wn0;
                    CP16(dstb + k * 784 + o * 256 + n16 * 16,
                         gWc + (size_t)o * (CIN * HD) + (size_t)(k1 + k) * HD + n16 * 8);
                }
        }
        CP_COMMIT();                      // empty group on last iter keeps cadence
        CP_WAIT(1);                       // W stage (it&1) complete
        __syncthreads();                  // Xs stored + W visible

        const u32 wb = Ws_b + (it & 1) * (WSTG * 2);
        #pragma unroll
        for (int ks = 0; ks < 2; ks++) {
            u32 ah[2][4];
            #pragma unroll
            for (int mf = 0; mf < 2; mf++)
                ldsm4(Xs_b + ga_off[mf] + ks * 32, ah[mf][0], ah[mf][1], ah[mf][2], ah[mf][3]);
            #pragma unroll
            for (int nf2 = 0; nf2 < 6; nf2++) {
                u32 b0, b1, b2, b3;
                ldsm4t(wb + bT_off + ks * (16 * 784) + nf2 * 32, b0, b1, b2, b3);
                #pragma unroll
                for (int mf = 0; mf < 2; mf++) {
                    mma_f16(acc[mf][2 * nf2],     ah[mf], b0, b1);
                    mma_f16(acc[mf][2 * nf2 + 1], ah[mf], b2, b3);
                }
            }
        }
    }

    // Epilogue: route each n-frag to its output (Q scaled by 1/32), fp16 stores
    #pragma unroll
    for (int mf = 0; mf < 2; mf++) {
        const size_t r = m0 + wm * 32 + mf * 16 + g;
        #pragma unroll
        for (int nf = 0; nf < 12; nf++) {
            const int gn  = wh * 96 + nf * 8 + qd;
            const int o   = gn >> 7;
            const int col = gn & 127;
            const float sc = (o == 0) ? 0.03125f : 1.0f;
            __half* G = (o == 0) ? gQ : (o == 1 ? gK : gV);
            *reinterpret_cast<u32*>(&G[r * HD + col]) =
                pack_half2(acc[mf][nf][0] * sc, acc[mf][nf][1] * sc);
            *reinterpret_cast<u32*>(&G[(r + 8) * HD + col]) =
                pack_half2(acc[mf][nf][2] * sc, acc[mf][nf][3] * sc);
        }
    }
}

// ---------------------------------------------------------------------------
// Kernel C: causal flash attention, fp16, PAIRED grid + split-KV warp groups.
// (unchanged from round 12 — passing at 44.1us)
// ---------------------------------------------------------------------------
#define AST 136                      // smem row stride in halves (272 B)
#define TILE_B (64 * AST * 2)        // one 64x128 fp16 tile: 17408 B
#define ATTN_SMEM (6 * TILE_B)       // per group: K0 K1 V -> 104448 B total

__device__ __forceinline__ void cp_tile64(u32 dst, const __half* src, int tg)
{
    #pragma unroll
    for (int i = 0; i < 8; i++) {         // 128 threads x 8 = 1024 chunks of 16B
        const int c   = tg + i * 128;
        const int row = c >> 4;           // 0..63
        const int col = c & 15;
        CP16(dst + row * 272 + col * 16, src + row * 128 + col * 8);
    }
}

__global__ __launch_bounds__(256) void attn_kernel(float* __restrict__ out)
{
    extern __shared__ __half sma[];
    const u32 base = smem_u32(sma);

    const int t    = threadIdx.x;
    const int lane = t & 31;
    const int warp = t >> 5;
    const int wg   = warp >> 2;           // 0 = group A (even jt), 1 = B (odd jt)
    const int w4   = warp & 3;            // warp within group -> q-rows w4*16..+15
    const int tg   = t & 127;             // thread id within group
    const int g    = lane >> 2;
    const int qd   = (lane & 3) << 1;
    const int j    = lane >> 3;
    const int lr   = lane & 7;
    const int b    = blockIdx.y;

    const u32 gbase = base + (u32)wg * 3 * TILE_B;
    const u32 K_s0 = gbase, K_s1 = gbase + TILE_B, V_b = gbase + 2 * TILE_B;

    const u32 a_off  = (w4 * 16 + ((j & 1) << 3) + lr) * 272 + ((j >> 1) << 4);
    const u32 kb_off = (((j >> 1) << 3) + lr) * 272 + ((j & 1) << 4);
    const u32 vb_off = (((j & 1) << 3) + lr) * 272 + ((j >> 1) << 4);

    #pragma unroll 1
    for (int half = 0; half < 2; half++) {
        const int qt = (half == 0) ? (31 - (int)blockIdx.x) : (int)blockIdx.x;
        const int i0 = qt * 64;
        const int n_g = (qt >= wg) ? (((qt - wg) >> 1) + 1) : 0;

        float O[16][4];
        #pragma unroll
        for (int nf = 0; nf < 16; nf++)
            #pragma unroll
            for (int e = 0; e < 4; e++) O[nf][e] = 0.f;
        float mrow[2] = {-1e30f, -1e30f};
        float lrow[2] = {0.f, 0.f};

        if (n_g > 0) {
            cp_tile64(K_s0, gK + ((size_t)b * TT + wg * 64) * HD, tg);
            cp_tile64(V_b,  gV + ((size_t)b * TT + wg * 64) * HD, tg);
            cp_tile64(K_s1, gQ + ((size_t)b * TT + i0) * HD, tg);
            CP_COMMIT();
            CP_WAIT(0);
            BAR_GRP(wg + 1);

            u32 qh[8][4];
            #pragma unroll
            for (int ks = 0; ks < 8; ks++)
                ldsm4(K_s1 + a_off + ks * 32, qh[ks][0], qh[ks][1], qh[ks][2], qh[ks][3]);

            for (int i = 0; i < n_g; i++) {
                const int jt = wg + 2 * i;
                const int stage = i & 1;
                const u32 kh = stage ? K_s1 : K_s0;

                CP_WAIT(1);              // K(i) complete (V(i) may be in flight)
                BAR_GRP(wg + 1);

                if (i + 1 < n_g)
                    cp_tile64(stage ? K_s0 : K_s1,
                              gK + ((size_t)b * TT + (jt + 2) * 64) * HD, tg);
                CP_COMMIT();             // empty group keeps wait cadence uniform

                float s[8][4];
                #pragma unroll
                for (int nf = 0; nf < 8; nf++)
                    #pragma unroll
                    for (int e = 0; e < 4; e++) s[nf][e] = 0.f;

                #pragma unroll
                for (int ks = 0; ks < 8; ks++) {
                    #pragma unroll
                    for (int nf2 = 0; nf2 < 4; nf2++) {
                        u32 b0, b1, b2, b3;
                        ldsm4(kh + kb_off + nf2 * (16 * 272) + ks * 32, b0, b1, b2, b3);
                        mma_f16(s[2 * nf2],     qh[ks], b0, b1);
                        mma_f16(s[2 * nf2 + 1], qh[ks], b2, b3);
                    }
                }

                if (jt == qt) {
                    #pragma unroll
                    for (int nf = 0; nf < 8; nf++) {
                        const int c0 = nf * 8 + qd;
                        const int r0 = w4 * 16 + g;
                        if (c0     > r0)     s[nf][0] = -1e30f;
                        if (c0 + 1 > r0)     s[nf][1] = -1e30f;
                        if (c0     > r0 + 8) s[nf][2] = -1e30f;
                        if (c0 + 1 > r0 + 8) s[nf][3] = -1e30f;
                    }
                }

                float mx0 = -1e30f, mx1 = -1e30f;
                #pragma unroll
                for (int nf = 0; nf < 8; nf++) {
                    mx0 = fmaxf(mx0, fmaxf(s[nf][0], s[nf][1]));
                    mx1 = fmaxf(mx1, fmaxf(s[nf][2], s[nf][3]));
                }
                mx0 = fmaxf(mx0, __shfl_xor_sync(0xffffffffu, mx0, 1));
                mx0 = fmaxf(mx0, __shfl_xor_sync(0xffffffffu, mx0, 2));
                mx1 = fmaxf(mx1, __shfl_xor_sync(0xffffffffu, mx1, 1));
                mx1 = fmaxf(mx1, __shfl_xor_sync(0xffffffffu, mx1, 2));
                const float mn0 = fmaxf(mrow[0], mx0);
                const float mn1 = fmaxf(mrow[1], mx1);
                const float a0  = __expf(mrow[0] - mn0);
                const float a1  = __expf(mrow[1] - mn1);
                mrow[0] = mn0; mrow[1] = mn1;

                float sum0 = 0.f, sum1 = 0.f;
                #pragma unroll
                for (int nf = 0; nf < 8; nf++) {
                    s[nf][0] = __expf(s[nf][0] - mn0);
                    s[nf][1] = __expf(s[nf][1] - mn0);
                    s[nf][2] = __expf(s[nf][2] - mn1);
                    s[nf][3] = __expf(s[nf][3] - mn1);
                    sum0 += s[nf][0] + s[nf][1];
                    sum1 += s[nf][2] + s[nf][3];
                }
                sum0 += __shfl_xor_sync(0xffffffffu, sum0, 1);
                sum0 += __shfl_xor_sync(0xffffffffu, sum0, 2);
                sum1 += __shfl_xor_sync(0xffffffffu, sum1, 1);
                sum1 += __shfl_xor_sync(0xffffffffu, sum1, 2);
                lrow[0] = lrow[0] * a0 + sum0;
                lrow[1] = lrow[1] * a1 + sum1;

                #pragma unroll
                for (int nf = 0; nf < 16; nf++) {
                    O[nf][0] *= a0; O[nf][1] *= a0;
                    O[nf][2] *= a1; O[nf][3] *= a1;
                }

                CP_WAIT(1);              // V(i) complete
                BAR_GRP(wg + 1);

                #pragma unroll
                for (int ks = 0; ks < 4; ks++) {
                    u32 ph[4];
                    ph[0] = pack_half2(s[2 * ks][0],     s[2 * ks][1]);
                    ph[1] = pack_half2(s[2 * ks][2],     s[2 * ks][3]);
                    ph[2] = pack_half2(s[2 * ks + 1][0], s[2 * ks + 1][1]);
                    ph[3] = pack_half2(s[2 * ks + 1][2], s[2 * ks + 1][3]);
                    #pragma unroll
                    for (int nf2 = 0; nf2 < 8; nf2++) {
                        u32 b0, b1, b2, b3;
                        ldsm4t(V_b + vb_off + ks * (16 * 272) + nf2 * 32, b0, b1, b2, b3);
                        mma_f16(O[2 * nf2],     ph, b0, b1);
                        mma_f16(O[2 * nf2 + 1], ph, b2, b3);
                    }
                }

                BAR_GRP(wg + 1);         // group done reading V before overwrite
                if (i + 1 < n_g)
                    cp_tile64(V_b, gV + ((size_t)b * TT + (jt + 2) * 64) * HD, tg);
                CP_COMMIT();
            }
            CP_WAIT(0);
        }

        // ---- merge group B partials into A, then A stores ----
        float* ex = reinterpret_cast<float*>(reinterpret_cast<char*>(sma) + 3 * TILE_B);
        if (wg == 1) {
            float* p = ex + tg * 68;
            #pragma unroll
            for (int nf = 0; nf < 16; nf++) {
                p[nf * 4 + 0] = O[nf][0]; p[nf * 4 + 1] = O[nf][1];
                p[nf * 4 + 2] = O[nf][2]; p[nf * 4 + 3] = O[nf][3];
            }
            p[64] = mrow[0]; p[65] = mrow[1];
            p[66] = lrow[0]; p[67] = lrow[1];
        }
        __syncthreads();
        if (wg == 0) {
            const float* p = ex + tg * 68;
            const float mB0 = p[64], mB1 = p[65], lB0 = p[66], lB1 = p[67];
            const float m0 = fmaxf(mrow[0], mB0);
            const float m1 = fmaxf(mrow[1], mB1);
            const float aA0 = __expf(mrow[0] - m0), aB0 = __expf(mB0 - m0);
            const float aA1 = __expf(mrow[1] - m1), aB1 = __expf(mB1 - m1);
            const float inv0 = 1.0f / (lrow[0] * aA0 + lB0 * aB0);
            const float inv1 = 1.0f / (lrow[1] * aA1 + lB1 * aB1);
            const size_t r0 = (size_t)b * TT + i0 + w4 * 16 + g;
            #pragma unroll
            for (int nf = 0; nf < 16; nf++) {
                const int col = nf * 8 + qd;
                float2 v0 = make_float2(
                    (O[nf][0] * aA0 + p[nf * 4 + 0] * aB0) * inv0,
                    (O[nf][1] * aA0 + p[nf * 4 + 1] * aB0) * inv0);
                float2 v1 = make_float2(
                    (O[nf][2] * aA1 + p[nf * 4 + 2] * aB1) * inv1,
                    (O[nf][3] * aA1 + p[nf * 4 + 3] * aB1) * inv1);
                *reinterpret_cast<float2*>(out + r0 * HD + col)       = v0;
                *reinterpret_cast<float2*>(out + (r0 + 8) * HD + col) = v1;
            }
        }
        __syncthreads();     // protect exchange area before next half's prologue
    }
}

// ---------------------------------------------------------------------------
extern "C" void kernel_launch(void* const* d_in, const int* in_sizes, int n_in,
                              void* d_out, int out_size)
{
    const float* X  = (const float*)d_in[0];   // [8,2048,1024]
    const float* Wq = (const float*)d_in[1];   // [1024,128]
    const float* Wk = (const float*)d_in[2];
    const float* Wv = (const float*)d_in[3];
    float* out = (float*)d_out;                // [8,2048,128]
    (void)in_sizes; (void)n_in; (void)out_size;

    cudaFuncSetAttribute(qkv_mma,
        cudaFuncAttributeMaxDynamicSharedMemorySize, GEMM_SMEM);
    cudaFuncSetAttribute(attn_kernel,
        cudaFuncAttributeMaxDynamicSharedMemorySize, ATTN_SMEM);

    convert_w<<<3 * CIN * HD / (256 * 8), 256>>>(Wq, Wk, Wv);
    qkv_mma<<<BT / 64, 256, GEMM_SMEM>>>(X);
    attn_kernel<<<dim3(16, BB), 256, ATTN_SMEM>>>(out);
}

// round 15
// speedup vs baseline: 1.6276x; 1.1055x over previous
#include <cuda_runtime.h>
#include <cuda_fp16.h>
#include <cstdint>

#define BB   8
#define TT   2048
#define CIN  1024
#define HD   128
#define BT   (BB*TT)          // 16384 rows

typedef unsigned int u32;

// ---------------------------------------------------------------------------
// Device scratch (static globals: allocation-guard safe). fp16.
// ---------------------------------------------------------------------------
__device__ __align__(256) __half gQ[(size_t)BT * HD];
__device__ __align__(256) __half gK[(size_t)BT * HD];
__device__ __align__(256) __half gV[(size_t)BT * HD];
__device__ __align__(256) __half gWc[3 * CIN * HD];   // fp16 W, [o][k][n]

// ---------------------------------------------------------------------------
// Helpers
// ---------------------------------------------------------------------------
__device__ __forceinline__ u32 pack_half2(float x, float y) {
    __half2 h = __floats2half2_rn(x, y);
    return *reinterpret_cast<u32*>(&h);
}
__device__ __forceinline__ void mma_f16(float* d, const u32* a, u32 b0, u32 b1) {
    asm volatile(
        "mma.sync.aligned.m16n8k16.row.col.f32.f16.f16.f32 "
        "{%0,%1,%2,%3}, {%4,%5,%6,%7}, {%8,%9}, {%0,%1,%2,%3};"
        : "+f"(d[0]), "+f"(d[1]), "+f"(d[2]), "+f"(d[3])
        : "r"(a[0]), "r"(a[1]), "r"(a[2]), "r"(a[3]), "r"(b0), "r"(b1));
}
__device__ __forceinline__ u32 smem_u32(const void* p) {
    u32 a;
    asm("{ .reg .u64 t; cvta.to.shared.u64 t, %1; cvt.u32.u64 %0, t; }"
        : "=r"(a) : "l"(p));
    return a;
}
__device__ __forceinline__ void ldsm4(u32 a, u32& r0, u32& r1, u32& r2, u32& r3) {
    asm volatile("ldmatrix.sync.aligned.m8n8.x4.shared.b16 {%0,%1,%2,%3}, [%4];"
                 : "=r"(r0), "=r"(r1), "=r"(r2), "=r"(r3) : "r"(a));
}
__device__ __forceinline__ void ldsm4t(u32 a, u32& r0, u32& r1, u32& r2, u32& r3) {
    asm volatile("ldmatrix.sync.aligned.m8n8.x4.trans.shared.b16 {%0,%1,%2,%3}, [%4];"
                 : "=r"(r0), "=r"(r1), "=r"(r2), "=r"(r3) : "r"(a));
}
#define CP16(dst, src) \
    asm volatile("cp.async.cg.shared.global [%0], [%1], 16;" \
                 :: "r"(dst), "l"(src) : "memory")
#define CP_COMMIT() asm volatile("cp.async.commit_group;" ::: "memory")
#define CP_WAIT(n)  asm volatile("cp.async.wait_group %0;" :: "n"(n) : "memory")
#define BAR_GRP(id) asm volatile("bar.sync %0, 128;" :: "r"(id) : "memory")

// ---------------------------------------------------------------------------
// Kernel A: elementwise W fp32 -> fp16, [o][k][n] (no transpose; 8 elems/thr).
// ---------------------------------------------------------------------------
__global__ __launch_bounds__(256) void convert_w(const float* __restrict__ Wq,
                                                 const float* __restrict__ Wk,
                                                 const float* __restrict__ Wv)
{
    const size_t base = ((size_t)blockIdx.x * 256 + threadIdx.x) * 8;
    const int o = (int)(base >> 17);
    const int r = (int)(base & 131071);
    const float* W = (o == 0) ? Wq : (o == 1 ? Wk : Wv);
    float4 a = *reinterpret_cast<const float4*>(W + r);
    float4 b = *reinterpret_cast<const float4*>(W + r + 4);
    uint4 v;
    v.x = pack_half2(a.x, a.y); v.y = pack_half2(a.z, a.w);
    v.z = pack_half2(b.x, b.y); v.w = pack_half2(b.z, b.w);
    *reinterpret_cast<uint4*>(gWc + (size_t)o * (CIN * HD) + r) = v;
}

// ---------------------------------------------------------------------------
// Kernel B: FUSED QKV GEMM — one CTA computes Q,K,V (N=384) for 64 M-rows.
// BM=64, BK=32; 8 warps = 2 wm x 4 wh (warp: 32 m-rows x 96 n-cols).
// X: fp32 LDG reg-prefetch -> fp16 smem [m][k] DOUBLE-BUFFERED.
// W: fp16 cp.async double-buffered [k][384n], issued AFTER the barrier so the
//    2-stage ring is race-free with ONE __syncthreads per K-iteration.
// __launch_bounds__(256, 2): regs <= 128 -> 2 CTAs/SM -> 256 CTAs = 1 wave.
// ---------------------------------------------------------------------------
#define GS   40                           // X smem k-stride (halves)
#define XSTG (64 * GS)                    // halves per X stage
#define WST2 392                          // W smem n-stride (halves), 784 B
#define WSTG (32 * WST2)                  // halves per W stage
#define GEMM_SMEM ((2 * XSTG + 2 * WSTG) * 2)

__global__ __launch_bounds__(256, 2) void qkv_mma(const float* __restrict__ X)
{
    extern __shared__ __half smg[];
    const u32 Xs_b = smem_u32(smg);                   // 2 stages [64][GS]
    const u32 Ws_b = smem_u32(smg + 2 * XSTG);        // 2 stages [32][WST2]

    const int t    = threadIdx.x;
    const int lane = t & 31;
    const int wrp  = t >> 5;
    const int wm   = wrp & 1;             // m-group: rows wm*32..+31
    const int wh   = wrp >> 1;            // n-quarter: cols wh*96..+95
    const int g    = lane >> 2;
    const int qd   = (lane & 3) << 1;
    const int j    = lane >> 3;
    const int lr   = lane & 7;
    const size_t m0 = (size_t)blockIdx.x * 64;

    u32 ga_off[2];
    #pragma unroll
    for (int mf = 0; mf < 2; mf++)
        ga_off[mf] = (wm * 32 + mf * 16 + ((j & 1) << 3) + lr) * 80 + ((j >> 1) << 4);
    const u32 bT_off = (((j & 1) << 3) + lr) * 784 + ((j >> 1) << 4) + wh * 192;

    float acc[2][12][4];
    #pragma unroll
    for (int mf = 0; mf < 2; mf++)
        #pragma unroll
        for (int nf = 0; nf < 12; nf++)
            #pragma unroll
            for (int e = 0; e < 4; e++) acc[mf][nf][e] = 0.f;

    float4 xv[2];
    const int xr = t >> 3;                // X row base (0..31)
    const int xc = (t & 7) << 2;          // X col (floats)
    const int wk0 = t >> 4, wn0 = t & 15; // W cp.async indices

    // ---- prologue: X(0) into regs, W(0) into stage 0 ----
    #pragma unroll
    for (int i = 0; i < 2; i++)
        xv[i] = *reinterpret_cast<const float4*>(X + (m0 + xr + i * 32) * CIN + xc);
    #pragma unroll
    for (int o = 0; o < 3; o++)
        #pragma unroll
        for (int jj = 0; jj < 2; jj++) {
            const int k = wk0 + jj * 16;
            CP16(Ws_b + k * 784 + o * 256 + wn0 * 16,
                 gWc + (size_t)o * (CIN * HD) + (size_t)k * HD + wn0 * 8);
        }
    CP_COMMIT();

    for (int it = 0; it < 32; it++) {
        // ---- store X(it) into its stage (no barrier needed before: writer
        //      stage (it&1) was last read in MMA(it-2); sync(it-1) ordered it) ----
        __half* Xst = smg + (it & 1) * XSTG;
        #pragma unroll
        for (int i = 0; i < 2; i++) {
            const int r = xr + i * 32;
            *reinterpret_cast<u32*>(&Xst[r * GS + xc])     = pack_half2(xv[i].x, xv[i].y);
            *reinterpret_cast<u32*>(&Xst[r * GS + xc + 2]) = pack_half2(xv[i].z, xv[i].w);
        }
        if (it < 31) {
            const int k1 = (it + 1) * 32;
            #pragma unroll
            for (int i = 0; i < 2; i++)
                xv[i] = *reinterpret_cast<const float4*>(X + (m0 + xr + i * 32) * CIN + k1 + xc);
        }

        CP_WAIT(0);                       // W(it) complete (this thread's chunks)
        __syncthreads();                  // X(it) + W(it) visible CTA-wide

        // ---- issue W(it+1) AFTER the barrier: all warps are past MMA(it-1),
        //      so overwriting stage (it+1)&1 is safe ----
        if (it < 31) {
            const int k1 = (it + 1) * 32;
            const u32 dstb = Ws_b + ((it + 1) & 1) * (WSTG * 2);
            #pragma unroll
            for (int o = 0; o < 3; o++)
                #pragma unroll
                for (int jj = 0; jj < 2; jj++) {
                    const int k = wk0 + jj * 16;
                    CP16(dstb + k * 784 + o * 256 + wn0 * 16,
                         gWc + (size_t)o * (CIN * HD) + (size_t)(k1 + k) * HD + wn0 * 8);
                }
        }
        CP_COMMIT();

        const u32 xb = Xs_b + (it & 1) * (XSTG * 2);
        const u32 wb = Ws_b + (it & 1) * (WSTG * 2);
        #pragma unroll
        for (int ks = 0; ks < 2; ks++) {
            u32 ah[2][4];
            #pragma unroll
            for (int mf = 0; mf < 2; mf++)
                ldsm4(xb + ga_off[mf] + ks * 32, ah[mf][0], ah[mf][1], ah[mf][2], ah[mf][3]);
            #pragma unroll
            for (int nf2 = 0; nf2 < 6; nf2++) {
                u32 b0, b1, b2, b3;
                ldsm4t(wb + bT_off + ks * (16 * 784) + nf2 * 32, b0, b1, b2, b3);
                #pragma unroll
                for (int mf = 0; mf < 2; mf++) {
                    mma_f16(acc[mf][2 * nf2],     ah[mf], b0, b1);
                    mma_f16(acc[mf][2 * nf2 + 1], ah[mf], b2, b3);
                }
            }
        }
    }

    // Epilogue: route each n-frag to its output (Q scaled by 1/32), fp16 stores
    #pragma unroll
    for (int mf = 0; mf < 2; mf++) {
        const size_t r = m0 + wm * 32 + mf * 16 + g;
        #pragma unroll
        for (int nf = 0; nf < 12; nf++) {
            const int gn  = wh * 96 + nf * 8 + qd;
            const int o   = gn >> 7;
            const int col = gn & 127;
            const float sc = (o == 0) ? 0.03125f : 1.0f;
            __half* G = (o == 0) ? gQ : (o == 1 ? gK : gV);
            *reinterpret_cast<u32*>(&G[r * HD + col]) =
                pack_half2(acc[mf][nf][0] * sc, acc[mf][nf][1] * sc);
            *reinterpret_cast<u32*>(&G[(r + 8) * HD + col]) =
                pack_half2(acc[mf][nf][2] * sc, acc[mf][nf][3] * sc);
        }
    }
}

// ---------------------------------------------------------------------------
// Kernel C: causal flash attention, fp16, PAIRED grid + split-KV warp groups.
// (unchanged from round 12/14 — passing at 44.1us)
// ---------------------------------------------------------------------------
#define AST 136                      // smem row stride in halves (272 B)
#define TILE_B (64 * AST * 2)        // one 64x128 fp16 tile: 17408 B
#define ATTN_SMEM (6 * TILE_B)       // per group: K0 K1 V -> 104448 B total

__device__ __forceinline__ void cp_tile64(u32 dst, const __half* src, int tg)
{
    #pragma unroll
    for (int i = 0; i < 8; i++) {         // 128 threads x 8 = 1024 chunks of 16B
        const int c   = tg + i * 128;
        const int row = c >> 4;           // 0..63
        const int col = c & 15;
        CP16(dst + row * 272 + col * 16, src + row * 128 + col * 8);
    }
}

__global__ __launch_bounds__(256) void attn_kernel(float* __restrict__ out)
{
    extern __shared__ __half sma[];
    const u32 base = smem_u32(sma);

    const int t    = threadIdx.x;
    const int lane = t & 31;
    const int warp = t >> 5;
    const int wg   = warp >> 2;           // 0 = group A (even jt), 1 = B (odd jt)
    const int w4   = warp & 3;            // warp within group -> q-rows w4*16..+15
    const int tg   = t & 127;             // thread id within group
    const int g    = lane >> 2;
    const int qd   = (lane & 3) << 1;
    const int j    = lane >> 3;
    const int lr   = lane & 7;
    const int b    = blockIdx.y;

    const u32 gbase = base + (u32)wg * 3 * TILE_B;
    const u32 K_s0 = gbase, K_s1 = gbase + TILE_B, V_b = gbase + 2 * TILE_B;

    const u32 a_off  = (w4 * 16 + ((j & 1) << 3) + lr) * 272 + ((j >> 1) << 4);
    const u32 kb_off = (((j >> 1) << 3) + lr) * 272 + ((j & 1) << 4);
    const u32 vb_off = (((j & 1) << 3) + lr) * 272 + ((j >> 1) << 4);

    #pragma unroll 1
    for (int half = 0; half < 2; half++) {
        const int qt = (half == 0) ? (31 - (int)blockIdx.x) : (int)blockIdx.x;
        const int i0 = qt * 64;
        const int n_g = (qt >= wg) ? (((qt - wg) >> 1) + 1) : 0;

        float O[16][4];
        #pragma unroll
        for (int nf = 0; nf < 16; nf++)
            #pragma unroll
            for (int e = 0; e < 4; e++) O[nf][e] = 0.f;
        float mrow[2] = {-1e30f, -1e30f};
        float lrow[2] = {0.f, 0.f};

        if (n_g > 0) {
            cp_tile64(K_s0, gK + ((size_t)b * TT + wg * 64) * HD, tg);
            cp_tile64(V_b,  gV + ((size_t)b * TT + wg * 64) * HD, tg);
            cp_tile64(K_s1, gQ + ((size_t)b * TT + i0) * HD, tg);
            CP_COMMIT();
            CP_WAIT(0);
            BAR_GRP(wg + 1);

            u32 qh[8][4];
            #pragma unroll
            for (int ks = 0; ks < 8; ks++)
                ldsm4(K_s1 + a_off + ks * 32, qh[ks][0], qh[ks][1], qh[ks][2], qh[ks][3]);

            for (int i = 0; i < n_g; i++) {
                const int jt = wg + 2 * i;
                const int stage = i & 1;
                const u32 kh = stage ? K_s1 : K_s0;

                CP_WAIT(1);              // K(i) complete (V(i) may be in flight)
                BAR_GRP(wg + 1);

                if (i + 1 < n_g)
                    cp_tile64(stage ? K_s0 : K_s1,
                              gK + ((size_t)b * TT + (jt + 2) * 64) * HD, tg);
                CP_COMMIT();             // empty group keeps wait cadence uniform

                float s[8][4];
                #pragma unroll
                for (int nf = 0; nf < 8; nf++)
                    #pragma unroll
                    for (int e = 0; e < 4; e++) s[nf][e] = 0.f;

                #pragma unroll
                for (int ks = 0; ks < 8; ks++) {
                    #pragma unroll
                    for (int nf2 = 0; nf2 < 4; nf2++) {
                        u32 b0, b1, b2, b3;
                        ldsm4(kh + kb_off + nf2 * (16 * 272) + ks * 32, b0, b1, b2, b3);
                        mma_f16(s[2 * nf2],     qh[ks], b0, b1);
                        mma_f16(s[2 * nf2 + 1], qh[ks], b2, b3);
                    }
                }

                if (jt == qt) {
                    #pragma unroll
                    for (int nf = 0; nf < 8; nf++) {
                        const int c0 = nf * 8 + qd;
                        const int r0 = w4 * 16 + g;
                        if (c0     > r0)     s[nf][0] = -1e30f;
                        if (c0 + 1 > r0)     s[nf][1] = -1e30f;
                        if (c0     > r0 + 8) s[nf][2] = -1e30f;
                        if (c0 + 1 > r0 + 8) s[nf][3] = -1e30f;
                    }
                }

                float mx0 = -1e30f, mx1 = -1e30f;
                #pragma unroll
                for (int nf = 0; nf < 8; nf++) {
                    mx0 = fmaxf(mx0, fmaxf(s[nf][0], s[nf][1]));
                    mx1 = fmaxf(mx1, fmaxf(s[nf][2], s[nf][3]));
                }
                mx0 = fmaxf(mx0, __shfl_xor_sync(0xffffffffu, mx0, 1));
                mx0 = fmaxf(mx0, __shfl_xor_sync(0xffffffffu, mx0, 2));
                mx1 = fmaxf(mx1, __shfl_xor_sync(0xffffffffu, mx1, 1));
                mx1 = fmaxf(mx1, __shfl_xor_sync(0xffffffffu, mx1, 2));
                const float mn0 = fmaxf(mrow[0], mx0);
                const float mn1 = fmaxf(mrow[1], mx1);
                const float a0  = __expf(mrow[0] - mn0);
                const float a1  = __expf(mrow[1] - mn1);
                mrow[0] = mn0; mrow[1] = mn1;

                float sum0 = 0.f, sum1 = 0.f;
                #pragma unroll
                for (int nf = 0; nf < 8; nf++) {
                    s[nf][0] = __expf(s[nf][0] - mn0);
                    s[nf][1] = __expf(s[nf][1] - mn0);
                    s[nf][2] = __expf(s[nf][2] - mn1);
                    s[nf][3] = __expf(s[nf][3] - mn1);
                    sum0 += s[nf][0] + s[nf][1];
                    sum1 += s[nf][2] + s[nf][3];
                }
                sum0 += __shfl_xor_sync(0xffffffffu, sum0, 1);
                sum0 += __shfl_xor_sync(0xffffffffu, sum0, 2);
                sum1 += __shfl_xor_sync(0xffffffffu, sum1, 1);
                sum1 += __shfl_xor_sync(0xffffffffu, sum1, 2);
                lrow[0] = lrow[0] * a0 + sum0;
                lrow[1] = lrow[1] * a1 + sum1;

                #pragma unroll
                for (int nf = 0; nf < 16; nf++) {
                    O[nf][0] *= a0; O[nf][1] *= a0;
                    O[nf][2] *= a1; O[nf][3] *= a1;
                }

                CP_WAIT(1);              // V(i) complete
                BAR_GRP(wg + 1);

                #pragma unroll
                for (int ks = 0; ks < 4; ks++) {
                    u32 ph[4];
                    ph[0] = pack_half2(s[2 * ks][0],     s[2 * ks][1]);
                    ph[1] = pack_half2(s[2 * ks][2],     s[2 * ks][3]);
                    ph[2] = pack_half2(s[2 * ks + 1][0], s[2 * ks + 1][1]);
                    ph[3] = pack_half2(s[2 * ks + 1][2], s[2 * ks + 1][3]);
                    #pragma unroll
                    for (int nf2 = 0; nf2 < 8; nf2++) {
                        u32 b0, b1, b2, b3;
                        ldsm4t(V_b + vb_off + ks * (16 * 272) + nf2 * 32, b0, b1, b2, b3);
                        mma_f16(O[2 * nf2],     ph, b0, b1);
                        mma_f16(O[2 * nf2 + 1], ph, b2, b3);
                    }
                }

                BAR_GRP(wg + 1);         // group done reading V before overwrite
                if (i + 1 < n_g)
                    cp_tile64(V_b, gV + ((size_t)b * TT + (jt + 2) * 64) * HD, tg);
                CP_COMMIT();
            }
            CP_WAIT(0);
        }

        // ---- merge group B partials into A, then A stores ----
        float* ex = reinterpret_cast<float*>(reinterpret_cast<char*>(sma) + 3 * TILE_B);
        if (wg == 1) {
            float* p = ex + tg * 68;
            #pragma unroll
            for (int nf = 0; nf < 16; nf++) {
                p[nf * 4 + 0] = O[nf][0]; p[nf * 4 + 1] = O[nf][1];
                p[nf * 4 + 2] = O[nf][2]; p[nf * 4 + 3] = O[nf][3];
            }
            p[64] = mrow[0]; p[65] = mrow[1];
            p[66] = lrow[0]; p[67] = lrow[1];
        }
        __syncthreads();
        if (wg == 0) {
            const float* p = ex + tg * 68;
            const float mB0 = p[64], mB1 = p[65], lB0 = p[66], lB1 = p[67];
            const float m0 = fmaxf(mrow[0], mB0);
            const float m1 = fmaxf(mrow[1], mB1);
            const float aA0 = __expf(mrow[0] - m0), aB0 = __expf(mB0 - m0);
            const float aA1 = __expf(mrow[1] - m1), aB1 = __expf(mB1 - m1);
            const float inv0 = 1.0f / (lrow[0] * aA0 + lB0 * aB0);
            const float inv1 = 1.0f / (lrow[1] * aA1 + lB1 * aB1);
            const size_t r0 = (size_t)b * TT + i0 + w4 * 16 + g;
            #pragma unroll
            for (int nf = 0; nf < 16; nf++) {
                const int col = nf * 8 + qd;
                float2 v0 = make_float2(
                    (O[nf][0] * aA0 + p[nf * 4 + 0] * aB0) * inv0,
                    (O[nf][1] * aA0 + p[nf * 4 + 1] * aB0) * inv0);
                float2 v1 = make_float2(
                    (O[nf][2] * aA1 + p[nf * 4 + 2] * aB1) * inv1,
                    (O[nf][3] * aA1 + p[nf * 4 + 3] * aB1) * inv1);
                *reinterpret_cast<float2*>(out + r0 * HD + col)       = v0;
                *reinterpret_cast<float2*>(out + (r0 + 8) * HD + col) = v1;
            }
        }
        __syncthreads();     // protect exchange area before next half's prologue
    }
}

// ---------------------------------------------------------------------------
extern "C" void kernel_launch(void* const* d_in, const int* in_sizes, int n_in,
                              void* d_out, int out_size)
{
    const float* X  = (const float*)d_in[0];   // [8,2048,1024]
    const float* Wq = (const float*)d_in[1];   // [1024,128]
    const float* Wk = (const float*)d_in[2];
    const float* Wv = (const float*)d_in[3];
    float* out = (float*)d_out;                // [8,2048,128]
    (void)in_sizes; (void)n_in; (void)out_size;

    cudaFuncSetAttribute(qkv_mma,
        cudaFuncAttributeMaxDynamicSharedMemorySize, GEMM_SMEM);
    cudaFuncSetAttribute(attn_kernel,
        cudaFuncAttributeMaxDynamicSharedMemorySize, ATTN_SMEM);

    convert_w<<<3 * CIN * HD / (256 * 8), 256>>>(Wq, Wk, Wv);
    qkv_mma<<<BT / 64, 256, GEMM_SMEM>>>(X);
    attn_kernel<<<dim3(16, BB), 256, ATTN_SMEM>>>(out);
}